// round 2
// baseline (speedup 1.0000x reference)
#include <cuda_runtime.h>
#include <cuda_bf16.h>
#include <cstdint>

// Problem constants (fixed shapes for this problem)
#define N_NODES 50000
#define E_EDGES 800000
#define IN_F    256
#define HID_F   256
#define OUT_F   128
#define OUT_COLS (OUT_F + HID_F + OUT_F)   // 512

// ---------------- device scratch (allocation-free) ----------------
// Lifetime analysis lets s1 / s2 / t share one buffer:
//   s1 = A@X        (dead after h1 GEMM)
//   s2 = A@h1       (dead after h2 GEMM)
//   t  = relu MLP   (dead after final GEMM)
__device__ float g_bufA[(size_t)N_NODES * IN_F];   // s1, then s2, then t
__device__ float g_h1 [(size_t)N_NODES * HID_F];   // relu(A@X @ W1)

__device__ int   g_cnt[N_NODES];
__device__ int   g_row_start[N_NODES + 1];
__device__ int   g_ofs[N_NODES];
__device__ int   g_csr_src[E_EDGES];
__device__ float g_csr_w[E_EDGES];

// ---------------- CSR build ----------------
__global__ void zero_cnt_kernel() {
    int i = blockIdx.x * blockDim.x + threadIdx.x;
    if (i < N_NODES) g_cnt[i] = 0;
}

__global__ void count_kernel(const int* __restrict__ dst) {
    int e = blockIdx.x * blockDim.x + threadIdx.x;
    if (e < E_EDGES) atomicAdd(&g_cnt[dst[e]], 1);
}

// single-block exclusive scan over 50000 counts (1024 threads, ~49 elems each)
__global__ void scan_kernel() {
    __shared__ int sums[1024];
    const int t  = threadIdx.x;
    const int CH = (N_NODES + 1023) / 1024;   // 49
    const int base = t * CH;

    int s = 0;
    for (int i = 0; i < CH; i++) {
        int idx = base + i;
        if (idx < N_NODES) s += g_cnt[idx];
    }
    sums[t] = s;
    __syncthreads();
    for (int off = 1; off < 1024; off <<= 1) {
        int v = 0;
        if (t >= off) v = sums[t - off];
        __syncthreads();
        sums[t] += v;
        __syncthreads();
    }
    int run = (t == 0) ? 0 : sums[t - 1];   // exclusive prefix
    for (int i = 0; i < CH; i++) {
        int idx = base + i;
        if (idx < N_NODES) {
            g_row_start[idx] = run;
            g_ofs[idx]       = run;
            run += g_cnt[idx];
        }
    }
    if (t == 1023) g_row_start[N_NODES] = run;  // == E_EDGES
}

__global__ void scatter_kernel(const int* __restrict__ src,
                               const int* __restrict__ dst,
                               const float* __restrict__ w) {
    int e = blockIdx.x * blockDim.x + threadIdx.x;
    if (e >= E_EDGES) return;
    int d = dst[e];
    int p = atomicAdd(&g_ofs[d], 1);
    g_csr_src[p] = src[e];
    g_csr_w[p]   = w[e];
}

// ---------------- SPMM: gather form, one warp per dst row (F = 256) ----------
__global__ __launch_bounds__(256)
void spmm_csr_kernel(const float* __restrict__ x, float* __restrict__ out) {
    int warp = (blockIdx.x * blockDim.x + threadIdx.x) >> 5;
    int lane = threadIdx.x & 31;
    if (warp >= N_NODES) return;

    int beg = g_row_start[warp];
    int end = g_row_start[warp + 1];

    float4 acc0 = make_float4(0.f, 0.f, 0.f, 0.f);
    float4 acc1 = make_float4(0.f, 0.f, 0.f, 0.f);

    for (int e = beg; e < end; e++) {
        int   s = __ldg(&g_csr_src[e]);
        float w = __ldg(&g_csr_w[e]);
        const float4* xr = reinterpret_cast<const float4*>(x + (size_t)s * 256);
        float4 v0 = __ldg(&xr[lane]);
        float4 v1 = __ldg(&xr[lane + 32]);
        acc0.x = fmaf(w, v0.x, acc0.x);
        acc0.y = fmaf(w, v0.y, acc0.y);
        acc0.z = fmaf(w, v0.z, acc0.z);
        acc0.w = fmaf(w, v0.w, acc0.w);
        acc1.x = fmaf(w, v1.x, acc1.x);
        acc1.y = fmaf(w, v1.y, acc1.y);
        acc1.z = fmaf(w, v1.z, acc1.z);
        acc1.w = fmaf(w, v1.w, acc1.w);
    }

    float4* o = reinterpret_cast<float4*>(out + (size_t)warp * 256);
    o[lane]      = acc0;
    o[lane + 32] = acc1;
}

// ---------------- SGEMM: C[n,M] = op(A[n,K] @ B[K,M] + bias) ----------------
// 128x128 block tile, BK=8, 256 threads, 8x8 per thread. M mult of 128,
// K mult of 8. Optional second output (C2) and relu/bias.
#define BM 128
#define BN 128
#define BK 8
#define TM 8
#define TN 8

__global__ __launch_bounds__(256)
void sgemm_kernel(const float* __restrict__ A, const float* __restrict__ B,
                  const float* __restrict__ bias,
                  float* __restrict__ C, int ldc,
                  float* __restrict__ C2, int ldc2,
                  int n, int K, int M, int do_relu) {
    __shared__ float As[BK][BM];
    __shared__ float Bs[BK][BN];

    const int tid  = threadIdx.x;
    const int row0 = blockIdx.x * BM;
    const int col0 = blockIdx.y * BN;

    const int tx = tid & 15;    // 16 thread-cols * TN=8  -> 128
    const int ty = tid >> 4;    // 16 thread-rows * TM=8 -> 128

    const int arow = tid >> 1;         // 0..127
    const int acol = (tid & 1) * 4;    // 0 or 4
    const int brow = tid >> 5;         // 0..7
    const int bcol = (tid & 31) * 4;   // 0..124

    float acc[TM][TN];
#pragma unroll
    for (int i = 0; i < TM; i++)
#pragma unroll
        for (int j = 0; j < TN; j++) acc[i][j] = 0.f;

    for (int k0 = 0; k0 < K; k0 += BK) {
        float4 av = make_float4(0.f, 0.f, 0.f, 0.f);
        if (row0 + arow < n)
            av = *reinterpret_cast<const float4*>(A + (size_t)(row0 + arow) * K + k0 + acol);
        As[acol + 0][arow] = av.x;
        As[acol + 1][arow] = av.y;
        As[acol + 2][arow] = av.z;
        As[acol + 3][arow] = av.w;

        float4 bv = *reinterpret_cast<const float4*>(B + (size_t)(k0 + brow) * M + col0 + bcol);
        *reinterpret_cast<float4*>(&Bs[brow][bcol]) = bv;

        __syncthreads();

#pragma unroll
        for (int k = 0; k < BK; k++) {
            float a[TM], b[TN];
            float4 a0 = *reinterpret_cast<const float4*>(&As[k][ty * TM]);
            float4 a1 = *reinterpret_cast<const float4*>(&As[k][ty * TM + 4]);
            a[0] = a0.x; a[1] = a0.y; a[2] = a0.z; a[3] = a0.w;
            a[4] = a1.x; a[5] = a1.y; a[6] = a1.z; a[7] = a1.w;
            float4 b0 = *reinterpret_cast<const float4*>(&Bs[k][tx * TN]);
            float4 b1 = *reinterpret_cast<const float4*>(&Bs[k][tx * TN + 4]);
            b[0] = b0.x; b[1] = b0.y; b[2] = b0.z; b[3] = b0.w;
            b[4] = b1.x; b[5] = b1.y; b[6] = b1.z; b[7] = b1.w;
#pragma unroll
            for (int i = 0; i < TM; i++)
#pragma unroll
                for (int j = 0; j < TN; j++)
                    acc[i][j] = fmaf(a[i], b[j], acc[i][j]);
        }
        __syncthreads();
    }

#pragma unroll
    for (int i = 0; i < TM; i++) {
        int row = row0 + ty * TM + i;
        if (row >= n) continue;
#pragma unroll
        for (int j = 0; j < TN; j++) {
            int col = col0 + tx * TN + j;
            float v = acc[i][j];
            if (bias) v += __ldg(&bias[col]);
            if (do_relu) v = fmaxf(v, 0.f);
            C[(size_t)row * ldc + col] = v;
            if (C2) C2[(size_t)row * ldc2 + col] = v;
        }
    }
}

// ---------------- launch ----------------
extern "C" void kernel_launch(void* const* d_in, const int* in_sizes, int n_in,
                              void* d_out, int out_size) {
    const float* features = (const float*)d_in[0];
    const int*   edge_src = (const int*)  d_in[1];
    const int*   edge_dst = (const int*)  d_in[2];
    const float* edge_w   = (const float*)d_in[3];
    const float* W1       = (const float*)d_in[4];
    const float* W2       = (const float*)d_in[5];
    const float* mlp_w1   = (const float*)d_in[6];
    const float* mlp_b1   = (const float*)d_in[7];
    const float* mlp_w2   = (const float*)d_in[8];
    const float* mlp_b2   = (const float*)d_in[9];
    float* out = (float*)d_out;

    float *bufA, *h1;
    cudaGetSymbolAddress((void**)&bufA, g_bufA);
    cudaGetSymbolAddress((void**)&h1,  g_h1);

    // ---- CSR build (by destination) ----
    zero_cnt_kernel<<<(N_NODES + 255) / 256, 256>>>();
    count_kernel<<<(E_EDGES + 255) / 256, 256>>>(edge_dst);
    scan_kernel<<<1, 1024>>>();
    scatter_kernel<<<(E_EDGES + 255) / 256, 256>>>(edge_src, edge_dst, edge_w);

    const int spmm_blocks = (N_NODES * 32 + 255) / 256;

    // ---- hop 1: bufA = A @ X ; h1 = relu(bufA @ W1) (also to out cols [128,384)) ----
    spmm_csr_kernel<<<spmm_blocks, 256>>>(features, bufA);
    {
        dim3 grid((N_NODES + BM - 1) / BM, HID_F / BN);
        sgemm_kernel<<<grid, 256>>>(bufA, W1, nullptr,
                                    h1, HID_F,
                                    out + OUT_F, OUT_COLS,
                                    N_NODES, IN_F, HID_F, /*relu=*/1);
    }

    // ---- hop 2: bufA = A @ h1 ; h2 = bufA @ W2 -> out cols [384,512) ----
    spmm_csr_kernel<<<spmm_blocks, 256>>>(h1, bufA);
    {
        dim3 grid((N_NODES + BM - 1) / BM, OUT_F / BN);
        sgemm_kernel<<<grid, 256>>>(bufA, W2, nullptr,
                                    out + OUT_F + HID_F, OUT_COLS,
                                    nullptr, 0,
                                    N_NODES, HID_F, OUT_F, /*relu=*/0);
    }

    // ---- self MLP: bufA = relu(X @ mlp_w1 + b1) ; out cols [0,128) = bufA @ mlp_w2 + b2 ----
    {
        dim3 grid((N_NODES + BM - 1) / BM, HID_F / BN);
        sgemm_kernel<<<grid, 256>>>(features, mlp_w1, mlp_b1,
                                    bufA, HID_F,
                                    nullptr, 0,
                                    N_NODES, IN_F, HID_F, /*relu=*/1);
    }
    {
        dim3 grid((N_NODES + BM - 1) / BM, OUT_F / BN);
        sgemm_kernel<<<grid, 256>>>(bufA, mlp_w2, mlp_b2,
                                    out, OUT_COLS,
                                    nullptr, 0,
                                    N_NODES, HID_F, OUT_F, /*relu=*/0);
    }
}

// round 5
// speedup vs baseline: 2.1627x; 2.1627x over previous
#include <cuda_runtime.h>
#include <cuda_bf16.h>
#include <cstdint>

// Problem constants
#define N_NODES 50000
#define E_EDGES 800000
#define IN_F    256
#define HID_F   256
#define OUT_F   128
#define OUT_COLS (OUT_F + HID_F + OUT_F)   // 512

// ---------------- device scratch (allocation-free) ----------------
__device__ float g_bufA[(size_t)N_NODES * IN_F];   // s1 -> s2 -> mlp hidden
__device__ float g_h1 [(size_t)N_NODES * HID_F];   // relu(A@X @ W1)

__device__ int   g_cnt[N_NODES];
__device__ int   g_row_start[N_NODES + 1];
__device__ int   g_ofs[N_NODES];
__device__ int   g_csr_src[E_EDGES];
__device__ float g_csr_w[E_EDGES];

// transposed weights: Bt[n][k] (K contiguous) for mma.sync .col B operand
__device__ float g_W1t[HID_F * IN_F];    // 256 x 256
__device__ float g_W2t[OUT_F * HID_F];   // 128 x 256
__device__ float g_m1t[HID_F * IN_F];    // 256 x 256
__device__ float g_m2t[OUT_F * HID_F];   // 128 x 256

// ---------------- helpers ----------------
__device__ __forceinline__ uint32_t cvt_tf32(float f) {
    uint32_t r;
    asm("cvt.rna.tf32.f32 %0, %1;" : "=r"(r) : "f"(f));
    return r;
}
__device__ __forceinline__ void mma_tf32_16x8x8(float* d, const uint32_t* a, const uint32_t* b) {
    asm volatile(
        "mma.sync.aligned.m16n8k8.row.col.f32.tf32.tf32.f32 "
        "{%0,%1,%2,%3}, {%4,%5,%6,%7}, {%8,%9}, {%0,%1,%2,%3};\n"
        : "+f"(d[0]), "+f"(d[1]), "+f"(d[2]), "+f"(d[3])
        : "r"(a[0]), "r"(a[1]), "r"(a[2]), "r"(a[3]), "r"(b[0]), "r"(b[1]));
}

// ---------------- CSR build ----------------
__global__ void zero_cnt_kernel() {
    int i = blockIdx.x * blockDim.x + threadIdx.x;
    if (i < N_NODES) g_cnt[i] = 0;
}

__global__ void count_kernel(const int* __restrict__ dst) {
    int e = blockIdx.x * blockDim.x + threadIdx.x;
    if (e < E_EDGES) atomicAdd(&g_cnt[dst[e]], 1);
}

__global__ void scan_kernel() {
    __shared__ int sums[1024];
    const int t  = threadIdx.x;
    const int CH = (N_NODES + 1023) / 1024;
    const int base = t * CH;

    int s = 0;
    for (int i = 0; i < CH; i++) {
        int idx = base + i;
        if (idx < N_NODES) s += g_cnt[idx];
    }
    sums[t] = s;
    __syncthreads();
    for (int off = 1; off < 1024; off <<= 1) {
        int v = 0;
        if (t >= off) v = sums[t - off];
        __syncthreads();
        sums[t] += v;
        __syncthreads();
    }
    int run = (t == 0) ? 0 : sums[t - 1];
    for (int i = 0; i < CH; i++) {
        int idx = base + i;
        if (idx < N_NODES) {
            g_row_start[idx] = run;
            g_ofs[idx]       = run;
            run += g_cnt[idx];
        }
    }
    if (t == 1023) g_row_start[N_NODES] = run;
}

__global__ void scatter_kernel(const int* __restrict__ src,
                               const int* __restrict__ dst,
                               const float* __restrict__ w) {
    int e = blockIdx.x * blockDim.x + threadIdx.x;
    if (e >= E_EDGES) return;
    int d = dst[e];
    int p = atomicAdd(&g_ofs[d], 1);
    g_csr_src[p] = src[e];
    g_csr_w[p]   = w[e];
}

// ---------------- weight transpose: B[K,M] -> Bt[M,K] ----------------
__global__ void transpose_kernel(const float* __restrict__ B, float* __restrict__ Bt,
                                 int K, int M) {
    int idx = blockIdx.x * blockDim.x + threadIdx.x;
    if (idx >= K * M) return;
    int k = idx / M, m = idx % M;
    Bt[(size_t)m * K + k] = B[idx];
}

// ---------------- SPMM: gather form, one warp per dst row (F = 256) ----------
__global__ __launch_bounds__(256)
void spmm_csr_kernel(const float* __restrict__ x, float* __restrict__ out) {
    int warp = (blockIdx.x * blockDim.x + threadIdx.x) >> 5;
    int lane = threadIdx.x & 31;
    if (warp >= N_NODES) return;

    int beg = g_row_start[warp];
    int end = g_row_start[warp + 1];

    float4 acc0 = make_float4(0.f, 0.f, 0.f, 0.f);
    float4 acc1 = make_float4(0.f, 0.f, 0.f, 0.f);

    for (int e = beg; e < end; e++) {
        int   s = __ldg(&g_csr_src[e]);
        float w = __ldg(&g_csr_w[e]);
        const float4* xr = reinterpret_cast<const float4*>(x + (size_t)s * 256);
        float4 v0 = __ldg(&xr[lane]);
        float4 v1 = __ldg(&xr[lane + 32]);
        acc0.x = fmaf(w, v0.x, acc0.x);
        acc0.y = fmaf(w, v0.y, acc0.y);
        acc0.z = fmaf(w, v0.z, acc0.z);
        acc0.w = fmaf(w, v0.w, acc0.w);
        acc1.x = fmaf(w, v1.x, acc1.x);
        acc1.y = fmaf(w, v1.y, acc1.y);
        acc1.z = fmaf(w, v1.z, acc1.z);
        acc1.w = fmaf(w, v1.w, acc1.w);
    }

    float4* o = reinterpret_cast<float4*>(out + (size_t)warp * 256);
    o[lane]      = acc0;
    o[lane + 32] = acc1;
}

// ---------------- tf32 mma.sync GEMM --------------------------------------
// C[n, NT] = op(A[n,256] @ Bt[NT,256]^T [+bias]).  CTA tile 128x128, BK=32.
// 8 warps; warp tile 32x64 (2 x 8 m16n8k8 tiles per k-step, 4 k-steps/chunk).
// smem rows padded to 36 floats: fragment lds bank = (4r+c)%32 -> conflict-free,
// and 36*4=144B keeps float4 stores 16B-aligned.
#define GP 36

__global__ __launch_bounds__(256)
void tf32_gemm_kernel(const float* __restrict__ A, const float* __restrict__ Bt,
                      const float* __restrict__ bias,
                      float* __restrict__ C, int ldc,
                      float* __restrict__ C2, int ldc2,
                      int n, int do_relu) {
    constexpr int K = 256, BK = 32, NCH = K / BK;
    __shared__ uint32_t sA[128 * GP];
    __shared__ uint32_t sB[128 * GP];

    const int tid  = threadIdx.x;
    const int lane = tid & 31;
    const int wid  = tid >> 5;
    const int warp_m = wid & 3;          // 0..3 -> 32-row slices
    const int warp_n = wid >> 2;         // 0..1 -> 64-col slices
    const int row0 = blockIdx.x * 128;
    const int col0 = blockIdx.y * 128;

    const int g   = lane >> 2;   // group 0..7
    const int tig = lane & 3;    // 0..3

    float acc[2][8][4];
#pragma unroll
    for (int i = 0; i < 2; i++)
#pragma unroll
        for (int j = 0; j < 8; j++)
#pragma unroll
            for (int v = 0; v < 4; v++) acc[i][j][v] = 0.f;

    for (int ch = 0; ch < NCH; ch++) {
        const int k0 = ch * BK;
        // stage A: 128 rows x 32 cols -> 1024 float4, 4 per thread
#pragma unroll
        for (int i = 0; i < 4; i++) {
            int idx = tid + i * 256;
            int r = idx >> 3, c = (idx & 7) * 4;
            float4 v = make_float4(0.f, 0.f, 0.f, 0.f);
            int row = row0 + r;
            if (row < n)
                v = *reinterpret_cast<const float4*>(A + (size_t)row * K + k0 + c);
            uint32_t* p = &sA[r * GP + c];
            p[0] = cvt_tf32(v.x); p[1] = cvt_tf32(v.y);
            p[2] = cvt_tf32(v.z); p[3] = cvt_tf32(v.w);
        }
        // stage B: 128 rows (output cols) x 32 cols(k)
#pragma unroll
        for (int i = 0; i < 4; i++) {
            int idx = tid + i * 256;
            int r = idx >> 3, c = (idx & 7) * 4;
            float4 v = *reinterpret_cast<const float4*>(Bt + (size_t)(col0 + r) * K + k0 + c);
            uint32_t* p = &sB[r * GP + c];
            p[0] = cvt_tf32(v.x); p[1] = cvt_tf32(v.y);
            p[2] = cvt_tf32(v.z); p[3] = cvt_tf32(v.w);
        }
        __syncthreads();

#pragma unroll
        for (int ks = 0; ks < 4; ks++) {
            const int kb = ks * 8;
            uint32_t af[2][4];
#pragma unroll
            for (int mt = 0; mt < 2; mt++) {
                int r = warp_m * 32 + mt * 16 + g;
                af[mt][0] = sA[ r      * GP + kb + tig    ];
                af[mt][1] = sA[(r + 8) * GP + kb + tig    ];
                af[mt][2] = sA[ r      * GP + kb + tig + 4];
                af[mt][3] = sA[(r + 8) * GP + kb + tig + 4];
            }
            uint32_t bf[8][2];
#pragma unroll
            for (int j = 0; j < 8; j++) {
                int nn = warp_n * 64 + j * 8 + g;
                bf[j][0] = sB[nn * GP + kb + tig    ];
                bf[j][1] = sB[nn * GP + kb + tig + 4];
            }
#pragma unroll
            for (int mt = 0; mt < 2; mt++)
#pragma unroll
                for (int j = 0; j < 8; j++)
                    mma_tf32_16x8x8(acc[mt][j], af[mt], bf[j]);
        }
        __syncthreads();
    }

    // epilogue: c0,c1 -> (row, col=tig*2), c2,c3 -> (row+8, col=tig*2)
#pragma unroll
    for (int mt = 0; mt < 2; mt++) {
#pragma unroll
        for (int half = 0; half < 2; half++) {
            int row = row0 + warp_m * 32 + mt * 16 + half * 8 + g;
            if (row >= n) continue;
#pragma unroll
            for (int j = 0; j < 8; j++) {
                int col = col0 + warp_n * 64 + j * 8 + tig * 2;
                float v0 = acc[mt][j][half * 2 + 0];
                float v1 = acc[mt][j][half * 2 + 1];
                if (bias) { v0 += __ldg(&bias[col]); v1 += __ldg(&bias[col + 1]); }
                if (do_relu) { v0 = fmaxf(v0, 0.f); v1 = fmaxf(v1, 0.f); }
                *reinterpret_cast<float2*>(C + (size_t)row * ldc + col) = make_float2(v0, v1);
                if (C2)
                    *reinterpret_cast<float2*>(C2 + (size_t)row * ldc2 + col) = make_float2(v0, v1);
            }
        }
    }
}

// ---------------- launch ----------------
extern "C" void kernel_launch(void* const* d_in, const int* in_sizes, int n_in,
                              void* d_out, int out_size) {
    const float* features = (const float*)d_in[0];
    const int*   edge_src = (const int*)  d_in[1];
    const int*   edge_dst = (const int*)  d_in[2];
    const float* edge_w   = (const float*)d_in[3];
    const float* W1       = (const float*)d_in[4];
    const float* W2       = (const float*)d_in[5];
    const float* mlp_w1   = (const float*)d_in[6];
    const float* mlp_b1   = (const float*)d_in[7];
    const float* mlp_w2   = (const float*)d_in[8];
    const float* mlp_b2   = (const float*)d_in[9];
    float* out = (float*)d_out;

    float *bufA, *h1, *W1t, *W2t, *m1t, *m2t;
    cudaGetSymbolAddress((void**)&bufA, g_bufA);
    cudaGetSymbolAddress((void**)&h1,  g_h1);
    cudaGetSymbolAddress((void**)&W1t, g_W1t);
    cudaGetSymbolAddress((void**)&W2t, g_W2t);
    cudaGetSymbolAddress((void**)&m1t, g_m1t);
    cudaGetSymbolAddress((void**)&m2t, g_m2t);

    // ---- weight transposes (tiny) ----
    transpose_kernel<<<(IN_F * HID_F + 255) / 256, 256>>>(W1,     W1t, IN_F,  HID_F);
    transpose_kernel<<<(HID_F * OUT_F + 255) / 256, 256>>>(W2,     W2t, HID_F, OUT_F);
    transpose_kernel<<<(IN_F * HID_F + 255) / 256, 256>>>(mlp_w1, m1t, IN_F,  HID_F);
    transpose_kernel<<<(HID_F * OUT_F + 255) / 256, 256>>>(mlp_w2, m2t, HID_F, OUT_F);

    // ---- CSR build (by destination) ----
    zero_cnt_kernel<<<(N_NODES + 255) / 256, 256>>>();
    count_kernel<<<(E_EDGES + 255) / 256, 256>>>(edge_dst);
    scan_kernel<<<1, 1024>>>();
    scatter_kernel<<<(E_EDGES + 255) / 256, 256>>>(edge_src, edge_dst, edge_w);

    const int spmm_blocks = (N_NODES * 32 + 255) / 256;
    const int gx = (N_NODES + 127) / 128;   // 391

    // ---- hop 1: bufA = A @ X ; h1 = relu(bufA @ W1) (also out cols [128,384)) ----
    spmm_csr_kernel<<<spmm_blocks, 256>>>(features, bufA);
    tf32_gemm_kernel<<<dim3(gx, 2), 256>>>(bufA, W1t, nullptr,
                                           h1, HID_F,
                                           out + OUT_F, OUT_COLS,
                                           N_NODES, /*relu=*/1);

    // ---- hop 2: bufA = A @ h1 ; out cols [384,512) = bufA @ W2 ----
    spmm_csr_kernel<<<spmm_blocks, 256>>>(h1, bufA);
    tf32_gemm_kernel<<<dim3(gx, 1), 256>>>(bufA, W2t, nullptr,
                                           out + OUT_F + HID_F, OUT_COLS,
                                           nullptr, 0,
                                           N_NODES, /*relu=*/0);

    // ---- self MLP: bufA = relu(X @ mlp_w1 + b1) ; out cols [0,128) ----
    tf32_gemm_kernel<<<dim3(gx, 2), 256>>>(features, m1t, mlp_b1,
                                           bufA, HID_F,
                                           nullptr, 0,
                                           N_NODES, /*relu=*/1);
    tf32_gemm_kernel<<<dim3(gx, 1), 256>>>(bufA, m2t, mlp_b2,
                                           out, OUT_COLS,
                                           nullptr, 0,
                                           N_NODES, /*relu=*/0);
}